// round 3
// baseline (speedup 1.0000x reference)
#include <cuda_runtime.h>
#include <math.h>

#define B      64
#define T_ENC  1024
#define D_ENC  512
#define Q_DIM  1024
#define H      256
#define M      5
#define EPSC   1e-5f

// Scratch (no allocation allowed -> __device__ globals)
__device__ float g_h[B * H];        // hidden activations
__device__ float g_w[B * M];        // mixture weights (post-softmax + eps)
__device__ float g_sigma[B * M];    // softplus(sigma_hat) + eps
__device__ float g_mu[B * M];       // mu_prev + softplus(Delta_hat)

// ---------------------------------------------------------------------------
// K1: h = relu(x @ W1 + b1)   x:[B,Q_DIM]  W1:[Q_DIM,H]
// grid (8 col-chunks, 8 batch-chunks), 256 threads = 32 cols x 8 batches
// ---------------------------------------------------------------------------
__global__ void k1_gemm1(const float* __restrict__ x,
                         const float* __restrict__ W1,
                         const float* __restrict__ b1)
{
    __shared__ float xs[8][64];    // [local batch][k]
    __shared__ float ws[64][32];   // [k][local col] -- stride 32: conflict-free

    const int cb  = blockIdx.x;          // col chunk (32 cols)
    const int bbk = blockIdx.y;          // batch chunk (8 batches)
    const int tid = threadIdx.x;
    const int cc  = tid & 31;            // local col 0..31
    const int bl  = tid >> 5;            // local batch 0..7
    const int colbase = cb * 32;
    const int bbase   = bbk * 8;

    float acc = 0.f;

    for (int k0 = 0; k0 < Q_DIM; k0 += 64) {
        // load W1 tile: 64 rows x 32 cols; warp (bl) loads rows bl, bl+8, ...
        #pragma unroll
        for (int rr = 0; rr < 8; rr++) {
            int r = bl + rr * 8;
            ws[r][cc] = W1[(k0 + r) * H + colbase + cc];
        }
        // load x tile: 8 batches x 64 k = 512 elems, 2 per thread, coalesced
        #pragma unroll
        for (int i = 0; i < 2; i++) {
            int idx = tid + i * 256;
            int b   = idx >> 6;
            int kk  = idx & 63;
            xs[b][kk] = x[(bbase + b) * Q_DIM + k0 + kk];
        }
        __syncthreads();
        #pragma unroll
        for (int kk = 0; kk < 64; kk++)
            acc = fmaf(xs[bl][kk], ws[kk][cc], acc);   // xs broadcast in warp
        __syncthreads();
    }

    acc += b1[colbase + cc];
    g_h[(bbase + bl) * H + colbase + cc] = fmaxf(acc, 0.f);
}

// ---------------------------------------------------------------------------
// K2: params = h @ W2 + b2, then softmax / softplus transforms.
// grid (B), 32 threads (one warp per batch). Tiny.
// ---------------------------------------------------------------------------
__device__ __forceinline__ float softplusf(float v)
{
    return (v > 20.f) ? v : log1pf(expf(v));
}

__global__ void k2_params(const float* __restrict__ W2,
                          const float* __restrict__ b2,
                          const float* __restrict__ mu_prev)
{
    const int b    = blockIdx.x;
    const int lane = threadIdx.x;
    __shared__ float p[3 * M + 1];
    const float* h = &g_h[b * H];

    for (int j = 0; j < 3 * M; j++) {
        float s = 0.f;
        for (int k = lane; k < H; k += 32)
            s = fmaf(h[k], W2[k * (3 * M) + j], s);
        #pragma unroll
        for (int o = 16; o; o >>= 1)
            s += __shfl_down_sync(0xffffffffu, s, o);
        if (lane == 0) p[j] = s + b2[j];
    }
    __syncwarp();

    if (lane == 0) {
        // softmax over p[0..M)
        float mx = p[0];
        #pragma unroll
        for (int m = 1; m < M; m++) mx = fmaxf(mx, p[m]);
        float e[M], se = 0.f;
        #pragma unroll
        for (int m = 0; m < M; m++) { e[m] = expf(p[m] - mx); se += e[m]; }
        float inv = 1.f / se;
        #pragma unroll
        for (int m = 0; m < M; m++) g_w[b * M + m] = e[m] * inv + EPSC;
        #pragma unroll
        for (int m = 0; m < M; m++) {
            g_sigma[b * M + m] = softplusf(p[M + m]) + EPSC;
            g_mu[b * M + m]    = mu_prev[b * M + m] + softplusf(p[2 * M + m]);
        }
    }
}

// ---------------------------------------------------------------------------
// K3 (fused): alpha[b,t] = sum_m w_m*(f(z(t+1)) - f(z(t))), f(z)=1/(1+sigmoid(z))
//             context[b,d] += sum_t alpha[b,t] * memory[b,t,d]
// grid (B, 8 t-chunks), 128 threads. Each thread: 1 alpha, then one float4
// column slice over 128 rows (coalesced 2KB-row streaming). DRAM-bound.
// ---------------------------------------------------------------------------
__global__ void k3_alpha_ctx(const float* __restrict__ memory,
                             const unsigned char* __restrict__ mask,
                             float* __restrict__ out_ctx,
                             float* __restrict__ out_alpha)
{
    const int b    = blockIdx.x;
    const int base = blockIdx.y * 128;
    const int tid  = threadIdx.x;
    const int t    = base + tid;

    __shared__ float salpha[128];

    float w[M], sg[M], mu[M];
    #pragma unroll
    for (int m = 0; m < M; m++) {
        w[m]  = g_w[b * M + m];
        sg[m] = g_sigma[b * M + m];
        mu[m] = g_mu[b * M + m];
    }

    const float jv0 = (float)t + 0.5f;
    const float jv1 = (float)t + 1.5f;
    float a = 0.f;
    #pragma unroll
    for (int m = 0; m < M; m++) {
        float inv_s = 1.f / sg[m];
        float z0 = (mu[m] - jv0) * inv_s;
        float z1 = (mu[m] - jv1) * inv_s;
        float s0 = 1.f / (1.f + __expf(-z0));   // sigmoid; inf-safe at extremes
        float s1 = 1.f / (1.f + __expf(-z1));
        a += w[m] * (1.f / (1.f + s1) - 1.f / (1.f + s0));
    }
    if (a == 0.f) a = EPSC;                     // match jnp.where(alpha==0, eps)
    if (mask[b * T_ENC + t]) a = 0.f;

    out_alpha[b * T_ENC + t] = a;
    salpha[tid] = a;
    __syncthreads();

    float4 acc = make_float4(0.f, 0.f, 0.f, 0.f);
    const float4* mp =
        (const float4*)(memory + ((size_t)b * T_ENC + base) * D_ENC) + tid;
    #pragma unroll 4
    for (int r = 0; r < 128; r++) {
        float  av = salpha[r];
        float4 v  = mp[r * (D_ENC / 4)];
        acc.x = fmaf(av, v.x, acc.x);
        acc.y = fmaf(av, v.y, acc.y);
        acc.z = fmaf(av, v.z, acc.z);
        acc.w = fmaf(av, v.w, acc.w);
    }

    float* c = out_ctx + b * D_ENC + tid * 4;
    atomicAdd(c + 0, acc.x);
    atomicAdd(c + 1, acc.y);
    atomicAdd(c + 2, acc.z);
    atomicAdd(c + 3, acc.w);
}

// ---------------------------------------------------------------------------
extern "C" void kernel_launch(void* const* d_in, const int* in_sizes, int n_in,
                              void* d_out, int out_size)
{
    const float*         x       = (const float*)d_in[0];         // att_rnn_h [B,Q]
    const float*         memory  = (const float*)d_in[1];         // [B,T,D]
    const unsigned char* mask    = (const unsigned char*)d_in[2]; // [B,T] bool
    const float*         mu_prev = (const float*)d_in[3];         // [B,M]
    const float*         W1      = (const float*)d_in[4];         // [Q,256]
    const float*         b1      = (const float*)d_in[5];         // [256]
    const float*         W2      = (const float*)d_in[6];         // [256,15]
    const float*         b2      = (const float*)d_in[7];         // [15]

    float* out       = (float*)d_out;
    float* out_ctx   = out;                 // [B, D_ENC]
    float* out_alpha = out + B * D_ENC;     // [B, T_ENC]

    cudaMemsetAsync(out_ctx, 0, (size_t)B * D_ENC * sizeof(float));

    k1_gemm1<<<dim3(8, 8), 256>>>(x, W1, b1);
    k2_params<<<B, 32>>>(W2, b2, mu_prev);
    k3_alpha_ctx<<<dim3(B, 8), 128>>>(memory, mask, out_ctx, out_alpha);
}

// round 4
// speedup vs baseline: 1.7362x; 1.7362x over previous
#include <cuda_runtime.h>
#include <math.h>

#define B      64
#define T_ENC  1024
#define D_ENC  512
#define Q_DIM  1024
#define H      256
#define M      5
#define EPSC   1e-5f
#define KSPLIT 8

// Scratch (no allocation allowed -> __device__ globals)
__device__ float g_hp[KSPLIT * B * H]; // raw GEMM1 partial sums (no bias/relu)
__device__ float g_w[B * M];           // mixture weights (post-softmax + eps)
__device__ float g_sigma[B * M];       // softplus(sigma_hat) + eps
__device__ float g_mu[B * M];          // mu_prev + softplus(Delta_hat)

// ---------------------------------------------------------------------------
// K1: partial GEMM  g_hp[kz] += x[:,kz*128:+128] @ W1[kz*128:+128,:]
// grid (8 col-chunks, 8 batch-chunks, 8 k-splits), 256 thr = 32 cols x 8 b
// ---------------------------------------------------------------------------
__global__ void k1_gemm1(const float* __restrict__ x,
                         const float* __restrict__ W1)
{
    __shared__ float xs[8][64];    // [local batch][k]
    __shared__ float ws[64][32];   // [k][local col]

    const int cb  = blockIdx.x;
    const int bbk = blockIdx.y;
    const int kz  = blockIdx.z;
    const int tid = threadIdx.x;
    const int cc  = tid & 31;
    const int bl  = tid >> 5;
    const int colbase = cb * 32;
    const int bbase   = bbk * 8;
    const int kbase   = kz * (Q_DIM / KSPLIT);   // 128 K per block

    float acc = 0.f;

    #pragma unroll
    for (int kt = 0; kt < 2; kt++) {
        const int k0 = kbase + kt * 64;
        #pragma unroll
        for (int rr = 0; rr < 8; rr++) {
            int r = bl + rr * 8;
            ws[r][cc] = W1[(k0 + r) * H + colbase + cc];
        }
        #pragma unroll
        for (int i = 0; i < 2; i++) {
            int idx = tid + i * 256;
            int b   = idx >> 6;
            int kk  = idx & 63;
            xs[b][kk] = x[(bbase + b) * Q_DIM + k0 + kk];
        }
        __syncthreads();
        #pragma unroll
        for (int kk = 0; kk < 64; kk++)
            acc = fmaf(xs[bl][kk], ws[kk][cc], acc);
        __syncthreads();
    }

    g_hp[kz * (B * H) + (bbase + bl) * H + colbase + cc] = acc;
}

// ---------------------------------------------------------------------------
// K2: h = relu(sum_kz g_hp + b1); params = h @ W2 + b2; mixture transforms.
// grid (B), 256 threads (one block per batch).
// ---------------------------------------------------------------------------
__device__ __forceinline__ float softplusf(float v)
{
    return (v > 20.f) ? v : log1pf(expf(v));
}

__global__ void k2_params(const float* __restrict__ b1,
                          const float* __restrict__ W2,
                          const float* __restrict__ b2,
                          const float* __restrict__ mu_prev)
{
    const int b    = blockIdx.x;
    const int tid  = threadIdx.x;      // 256 = one h element each
    const int wid  = tid >> 5;
    const int lane = tid & 31;

    __shared__ float hs[H];
    __shared__ float p[3 * M + 1];

    float v = b1[tid];
    #pragma unroll
    for (int s = 0; s < KSPLIT; s++)
        v += g_hp[s * (B * H) + b * H + tid];
    hs[tid] = fmaxf(v, 0.f);
    __syncthreads();

    for (int j = wid; j < 3 * M; j += 8) {
        float s = 0.f;
        #pragma unroll
        for (int k = lane; k < H; k += 32)
            s = fmaf(hs[k], W2[k * (3 * M) + j], s);
        #pragma unroll
        for (int o = 16; o; o >>= 1)
            s += __shfl_down_sync(0xffffffffu, s, o);
        if (lane == 0) p[j] = s + b2[j];
    }
    __syncthreads();

    if (tid == 0) {
        float mx = p[0];
        #pragma unroll
        for (int m = 1; m < M; m++) mx = fmaxf(mx, p[m]);
        float e[M], se = 0.f;
        #pragma unroll
        for (int m = 0; m < M; m++) { e[m] = expf(p[m] - mx); se += e[m]; }
        float inv = 1.f / se;
        #pragma unroll
        for (int m = 0; m < M; m++) g_w[b * M + m] = e[m] * inv + EPSC;
        #pragma unroll
        for (int m = 0; m < M; m++) {
            g_sigma[b * M + m] = softplusf(p[M + m]) + EPSC;
            g_mu[b * M + m]    = mu_prev[b * M + m] + softplusf(p[2 * M + m]);
        }
    }
}

// ---------------------------------------------------------------------------
// K3 (fused): alpha + context streaming.
// grid (B, 16 t-chunks of 64), 128 threads. One float4 column slice/thread,
// 64 rows, unroll 8 with dual accumulators -> deep MLP, DRAM-bound.
// ---------------------------------------------------------------------------
#define TCHUNK 64

__global__ void k3_alpha_ctx(const float* __restrict__ memory,
                             const unsigned char* __restrict__ mask,
                             float* __restrict__ out_ctx,
                             float* __restrict__ out_alpha)
{
    const int b    = blockIdx.x;
    const int base = blockIdx.y * TCHUNK;
    const int tid  = threadIdx.x;

    __shared__ float salpha[TCHUNK];

    if (tid < TCHUNK) {
        const int t = base + tid;
        float a = 0.f;
        const float jv0 = (float)t + 0.5f;
        const float jv1 = (float)t + 1.5f;
        #pragma unroll
        for (int m = 0; m < M; m++) {
            float w  = g_w[b * M + m];
            float is = 1.f / g_sigma[b * M + m];
            float mu = g_mu[b * M + m];
            float z0 = (mu - jv0) * is;
            float z1 = (mu - jv1) * is;
            float s0 = 1.f / (1.f + __expf(-z0));
            float s1 = 1.f / (1.f + __expf(-z1));
            a += w * (1.f / (1.f + s1) - 1.f / (1.f + s0));
        }
        if (a == 0.f) a = EPSC;
        if (mask[b * T_ENC + t]) a = 0.f;
        out_alpha[b * T_ENC + t] = a;
        salpha[tid] = a;
    }
    __syncthreads();

    float4 acc0 = make_float4(0.f, 0.f, 0.f, 0.f);
    float4 acc1 = make_float4(0.f, 0.f, 0.f, 0.f);
    const float4* mp =
        (const float4*)(memory + ((size_t)b * T_ENC + base) * D_ENC) + tid;

    #pragma unroll 4
    for (int r = 0; r < TCHUNK; r += 2) {
        float  a0 = salpha[r];
        float  a1 = salpha[r + 1];
        float4 v0 = mp[(size_t)r * (D_ENC / 4)];
        float4 v1 = mp[(size_t)(r + 1) * (D_ENC / 4)];
        acc0.x = fmaf(a0, v0.x, acc0.x);
        acc0.y = fmaf(a0, v0.y, acc0.y);
        acc0.z = fmaf(a0, v0.z, acc0.z);
        acc0.w = fmaf(a0, v0.w, acc0.w);
        acc1.x = fmaf(a1, v1.x, acc1.x);
        acc1.y = fmaf(a1, v1.y, acc1.y);
        acc1.z = fmaf(a1, v1.z, acc1.z);
        acc1.w = fmaf(a1, v1.w, acc1.w);
    }
    acc0.x += acc1.x; acc0.y += acc1.y; acc0.z += acc1.z; acc0.w += acc1.w;

    float* c = out_ctx + b * D_ENC + tid * 4;
    atomicAdd(c + 0, acc0.x);
    atomicAdd(c + 1, acc0.y);
    atomicAdd(c + 2, acc0.z);
    atomicAdd(c + 3, acc0.w);
}

// ---------------------------------------------------------------------------
extern "C" void kernel_launch(void* const* d_in, const int* in_sizes, int n_in,
                              void* d_out, int out_size)
{
    const float*         x       = (const float*)d_in[0];
    const float*         memory  = (const float*)d_in[1];
    const unsigned char* mask    = (const unsigned char*)d_in[2];
    const float*         mu_prev = (const float*)d_in[3];
    const float*         W1      = (const float*)d_in[4];
    const float*         b1      = (const float*)d_in[5];
    const float*         W2      = (const float*)d_in[6];
    const float*         b2      = (const float*)d_in[7];

    float* out       = (float*)d_out;
    float* out_ctx   = out;                 // [B, D_ENC]
    float* out_alpha = out + B * D_ENC;     // [B, T_ENC]

    cudaMemsetAsync(out_ctx, 0, (size_t)B * D_ENC * sizeof(float));

    k1_gemm1<<<dim3(8, 8, KSPLIT), 256>>>(x, W1);
    k2_params<<<B, 256>>>(b1, W2, b2, mu_prev);
    k3_alpha_ctx<<<dim3(B, T_ENC / TCHUNK), 128>>>(memory, mask, out_ctx, out_alpha);
}

// round 5
// speedup vs baseline: 1.7469x; 1.0062x over previous
#include <cuda_runtime.h>
#include <math.h>

#define B      64
#define T_ENC  1024
#define D_ENC  512
#define Q_DIM  1024
#define H      256
#define M      5
#define EPSC   1e-5f
#define KSPLIT 32          // K elems per K1 block = Q_DIM/KSPLIT = 32

// Scratch (no allocation allowed -> __device__ globals)
__device__ float g_hp[KSPLIT * B * H]; // raw GEMM1 partial sums
__device__ float g_w[B * M];
__device__ float g_sigma[B * M];
__device__ float g_mu[B * M];

// ---------------------------------------------------------------------------
// K1: partial GEMM, register-tiled 4 batches x 4 cols per thread.
// grid (8 batch-chunks, KSPLIT), 128 threads = 64 col-quads x 2 batch-quads.
// W1 read directly from global (L2-resident, coalesced LDG.128).
// ---------------------------------------------------------------------------
__global__ void __launch_bounds__(128)
k1_gemm1(const float* __restrict__ x, const float* __restrict__ W1)
{
    const int KB = Q_DIM / KSPLIT;       // 32 k per block
    __shared__ float xs[8][KB];          // 8 batches x 32 k

    const int bbk   = blockIdx.x;        // batch chunk (8 batches)
    const int kz    = blockIdx.y;
    const int tid   = threadIdx.x;
    const int cq    = tid & 63;          // col quad: cols 4*cq .. 4*cq+3
    const int bq    = tid >> 6;          // batch quad: batches bq*4 .. bq*4+3
    const int bbase = bbk * 8;
    const int kbase = kz * KB;

    // load x tile: 8 x 32 = 256 floats, 2 per thread
    #pragma unroll
    for (int i = 0; i < 2; i++) {
        int idx = tid + i * 128;
        int b   = idx >> 5;
        int kk  = idx & 31;
        xs[b][kk] = x[(bbase + b) * Q_DIM + kbase + kk];
    }
    __syncthreads();

    float4 acc[4];
    #pragma unroll
    for (int i = 0; i < 4; i++) acc[i] = make_float4(0.f, 0.f, 0.f, 0.f);

    const float4* wp = (const float4*)(W1 + (size_t)kbase * H) + cq;

    #pragma unroll
    for (int k = 0; k < KB; k++) {
        float4 wv = wp[(size_t)k * (H / 4)];       // LDG.128, L2 hit
        #pragma unroll
        for (int i = 0; i < 4; i++) {
            float xb = xs[bq * 4 + i][k];          // LDS broadcast
            acc[i].x = fmaf(xb, wv.x, acc[i].x);
            acc[i].y = fmaf(xb, wv.y, acc[i].y);
            acc[i].z = fmaf(xb, wv.z, acc[i].z);
            acc[i].w = fmaf(xb, wv.w, acc[i].w);
        }
    }

    float4* hp = (float4*)(g_hp + (size_t)kz * (B * H)) ;
    #pragma unroll
    for (int i = 0; i < 4; i++)
        hp[(size_t)(bbase + bq * 4 + i) * (H / 4) + cq] = acc[i];
}

// ---------------------------------------------------------------------------
// K2: h = relu(sum_kz g_hp + b1); params = h @ W2 + b2; mixture transforms.
// grid (B), 256 threads.
// ---------------------------------------------------------------------------
__device__ __forceinline__ float softplusf(float v)
{
    return (v > 20.f) ? v : log1pf(expf(v));
}

__global__ void k2_params(const float* __restrict__ b1,
                          const float* __restrict__ W2,
                          const float* __restrict__ b2,
                          const float* __restrict__ mu_prev)
{
    const int b    = blockIdx.x;
    const int tid  = threadIdx.x;      // one h element each
    const int wid  = tid >> 5;
    const int lane = tid & 31;

    __shared__ float hs[H];
    __shared__ float p[3 * M + 1];

    float a0 = 0.f, a1 = 0.f, a2 = 0.f, a3 = 0.f;
    const float* hpb = g_hp + b * H + tid;
    #pragma unroll
    for (int s = 0; s < KSPLIT; s += 4) {
        a0 += hpb[(size_t)(s + 0) * (B * H)];
        a1 += hpb[(size_t)(s + 1) * (B * H)];
        a2 += hpb[(size_t)(s + 2) * (B * H)];
        a3 += hpb[(size_t)(s + 3) * (B * H)];
    }
    hs[tid] = fmaxf((a0 + a1) + (a2 + a3) + b1[tid], 0.f);
    __syncthreads();

    for (int j = wid; j < 3 * M; j += 8) {
        float s = 0.f;
        #pragma unroll
        for (int k = lane; k < H; k += 32)
            s = fmaf(hs[k], W2[k * (3 * M) + j], s);
        #pragma unroll
        for (int o = 16; o; o >>= 1)
            s += __shfl_down_sync(0xffffffffu, s, o);
        if (lane == 0) p[j] = s + b2[j];
    }
    __syncthreads();

    if (tid == 0) {
        float mx = p[0];
        #pragma unroll
        for (int m = 1; m < M; m++) mx = fmaxf(mx, p[m]);
        float e[M], se = 0.f;
        #pragma unroll
        for (int m = 0; m < M; m++) { e[m] = expf(p[m] - mx); se += e[m]; }
        float inv = 1.f / se;
        #pragma unroll
        for (int m = 0; m < M; m++) g_w[b * M + m] = e[m] * inv + EPSC;
        #pragma unroll
        for (int m = 0; m < M; m++) {
            g_sigma[b * M + m] = softplusf(p[M + m]) + EPSC;
            g_mu[b * M + m]    = mu_prev[b * M + m] + softplusf(p[2 * M + m]);
        }
    }
}

// ---------------------------------------------------------------------------
// K3 (fused): alpha + context streaming. DRAM-bound.
// grid (B, 16 t-chunks of 64), 128 threads, one float4 col-slice per thread.
// ---------------------------------------------------------------------------
#define TCHUNK 64

__global__ void k3_alpha_ctx(const float* __restrict__ memory,
                             const unsigned char* __restrict__ mask,
                             float* __restrict__ out_ctx,
                             float* __restrict__ out_alpha)
{
    const int b    = blockIdx.x;
    const int base = blockIdx.y * TCHUNK;
    const int tid  = threadIdx.x;

    __shared__ float salpha[TCHUNK];

    if (tid < TCHUNK) {
        const int t = base + tid;
        float a = 0.f;
        const float jv0 = (float)t + 0.5f;
        const float jv1 = (float)t + 1.5f;
        #pragma unroll
        for (int m = 0; m < M; m++) {
            float w  = g_w[b * M + m];
            float is = 1.f / g_sigma[b * M + m];
            float mu = g_mu[b * M + m];
            float z0 = (mu - jv0) * is;
            float z1 = (mu - jv1) * is;
            float s0 = 1.f / (1.f + __expf(-z0));
            float s1 = 1.f / (1.f + __expf(-z1));
            a += w * (1.f / (1.f + s1) - 1.f / (1.f + s0));
        }
        if (a == 0.f) a = EPSC;
        if (mask[b * T_ENC + t]) a = 0.f;
        out_alpha[b * T_ENC + t] = a;
        salpha[tid] = a;
    }
    __syncthreads();

    float4 acc0 = make_float4(0.f, 0.f, 0.f, 0.f);
    float4 acc1 = make_float4(0.f, 0.f, 0.f, 0.f);
    const float4* mp =
        (const float4*)(memory + ((size_t)b * T_ENC + base) * D_ENC) + tid;

    #pragma unroll 4
    for (int r = 0; r < TCHUNK; r += 2) {
        float  a0 = salpha[r];
        float  a1 = salpha[r + 1];
        float4 v0 = mp[(size_t)r * (D_ENC / 4)];
        float4 v1 = mp[(size_t)(r + 1) * (D_ENC / 4)];
        acc0.x = fmaf(a0, v0.x, acc0.x);
        acc0.y = fmaf(a0, v0.y, acc0.y);
        acc0.z = fmaf(a0, v0.z, acc0.z);
        acc0.w = fmaf(a0, v0.w, acc0.w);
        acc1.x = fmaf(a1, v1.x, acc1.x);
        acc1.y = fmaf(a1, v1.y, acc1.y);
        acc1.z = fmaf(a1, v1.z, acc1.z);
        acc1.w = fmaf(a1, v1.w, acc1.w);
    }
    acc0.x += acc1.x; acc0.y += acc1.y; acc0.z += acc1.z; acc0.w += acc1.w;

    float* c = out_ctx + b * D_ENC + tid * 4;
    atomicAdd(c + 0, acc0.x);
    atomicAdd(c + 1, acc0.y);
    atomicAdd(c + 2, acc0.z);
    atomicAdd(c + 3, acc0.w);
}

// ---------------------------------------------------------------------------
extern "C" void kernel_launch(void* const* d_in, const int* in_sizes, int n_in,
                              void* d_out, int out_size)
{
    const float*         x       = (const float*)d_in[0];
    const float*         memory  = (const float*)d_in[1];
    const unsigned char* mask    = (const unsigned char*)d_in[2];
    const float*         mu_prev = (const float*)d_in[3];
    const float*         W1      = (const float*)d_in[4];
    const float*         b1      = (const float*)d_in[5];
    const float*         W2      = (const float*)d_in[6];
    const float*         b2      = (const float*)d_in[7];

    float* out       = (float*)d_out;
    float* out_ctx   = out;                 // [B, D_ENC]
    float* out_alpha = out + B * D_ENC;     // [B, T_ENC]

    cudaMemsetAsync(out_ctx, 0, (size_t)B * D_ENC * sizeof(float));

    k1_gemm1<<<dim3(8, KSPLIT), 128>>>(x, W1);
    k2_params<<<B, 256>>>(b1, W2, b2, mu_prev);
    k3_alpha_ctx<<<dim3(B, T_ENC / TCHUNK), 128>>>(memory, mask, out_ctx, out_alpha);
}